// round 1
// baseline (speedup 1.0000x reference)
#include <cuda_runtime.h>
#include <math.h>

// ---------------- problem constants ----------------
#define BATCH 16
#define SEQL  513
#define DMODEL 768
#define NHEAD 12
#define DHEAD 64
#define FFDIM 3072
#define NLAYER 12
#define NPATCH1 512
#define NPATCH2 128
#define PATCHE 256      // 16*16
#define STLEN 385       // NPATCH - NSP + 1

// ---------------- scratch (device globals; no runtime alloc) ----------------
__device__ float g_z  [BATCH*SEQL*DMODEL];          // residual stream
__device__ float g_ln [BATCH*SEQL*DMODEL];          // layernorm output
__device__ float g_qkv[BATCH*SEQL*3*DMODEL];        // qkv projection
__device__ float g_q  [BATCH*NHEAD*SEQL*DHEAD];
__device__ float g_k  [BATCH*NHEAD*SEQL*DHEAD];
__device__ float g_v  [BATCH*NHEAD*SEQL*DHEAD];
__device__ float g_att[(size_t)BATCH*NHEAD*SEQL*SEQL];  // attention scores/probs
__device__ float g_o  [BATCH*SEQL*DMODEL];          // attention output (assembled)
__device__ float g_ff [BATCH*SEQL*FFDIM];           // FF hidden / embed scratch
__device__ float g_pool[BATCH*DMODEL];
__device__ float g_hln [BATCH*DMODEL];
__device__ float g_h1  [BATCH*256];
__device__ float g_h2  [BATCH*64];

// ---------------- generic fp32 GEMM: C[M,N] = A[M,K]@B[K,N] (+bias)(+gelu)(+res) ----
// Requirements: K % 8 == 0, N % 128 == 0 (true for all call sites). M ragged OK.
__global__ __launch_bounds__(256) void sgemm128(
    const float* __restrict__ A, const float* __restrict__ B,
    float* __restrict__ C, const float* __restrict__ bias,
    const float* __restrict__ res, int M, int N, int K, int act)
{
    __shared__ float As[8][128];
    __shared__ float Bs[8][128];
    const int tid = threadIdx.x;
    const int row0 = blockIdx.y * 128;
    const int col0 = blockIdx.x * 128;
    const int tr = tid >> 4;        // 0..15
    const int tc = tid & 15;        // 0..15

    float acc[8][8];
#pragma unroll
    for (int i = 0; i < 8; i++)
#pragma unroll
        for (int j = 0; j < 8; j++) acc[i][j] = 0.f;

    const int arow = tid >> 1;            // 0..127
    const int acol = (tid & 1) << 2;      // 0 or 4
    const int brow = tid >> 5;            // 0..7
    const int bcol = (tid & 31) << 2;     // 0..124

    const bool avalid = (row0 + arow) < M;
    const float* Aptr = A + (size_t)(row0 + arow) * K + acol;
    const float* Bptr = B + (size_t)brow * N + col0 + bcol;

    for (int k0 = 0; k0 < K; k0 += 8) {
        float4 av = make_float4(0.f, 0.f, 0.f, 0.f);
        if (avalid) av = *(const float4*)(Aptr + k0);
        float4 bv = *(const float4*)(Bptr + (size_t)k0 * N);
        __syncthreads();
        As[acol + 0][arow] = av.x;
        As[acol + 1][arow] = av.y;
        As[acol + 2][arow] = av.z;
        As[acol + 3][arow] = av.w;
        *(float4*)&Bs[brow][bcol] = bv;
        __syncthreads();
#pragma unroll
        for (int kk = 0; kk < 8; kk++) {
            float a[8], b[8];
            *(float4*)(a)     = *(const float4*)&As[kk][tr * 8];
            *(float4*)(a + 4) = *(const float4*)&As[kk][tr * 8 + 4];
            *(float4*)(b)     = *(const float4*)&Bs[kk][tc * 8];
            *(float4*)(b + 4) = *(const float4*)&Bs[kk][tc * 8 + 4];
#pragma unroll
            for (int i = 0; i < 8; i++)
#pragma unroll
                for (int j = 0; j < 8; j++)
                    acc[i][j] = fmaf(a[i], b[j], acc[i][j]);
        }
    }

#pragma unroll
    for (int i = 0; i < 8; i++) {
        int r = row0 + tr * 8 + i;
        if (r >= M) continue;
#pragma unroll
        for (int j = 0; j < 8; j++) {
            int c = col0 + tc * 8 + j;
            float vv = acc[i][j];
            if (bias) vv += bias[c];
            if (act)  vv = vv * normcdff(vv);   // exact GELU: x * Phi(x)
            if (res)  vv += res[(size_t)r * N + c];
            C[(size_t)r * N + c] = vv;
        }
    }
}

// ---------------- layernorm: one block per row of 768 ----------------
__global__ __launch_bounds__(256) void layernorm_k(
    const float* __restrict__ x, float* __restrict__ y,
    const float* __restrict__ s, const float* __restrict__ b)
{
    int row = blockIdx.x;
    const float* xr = x + (size_t)row * DMODEL;
    float* yr = y + (size_t)row * DMODEL;
    int tid = threadIdx.x;
    float v0 = xr[tid], v1 = xr[tid + 256], v2 = xr[tid + 512];
    float sum = v0 + v1 + v2;
    float sq  = fmaf(v0, v0, fmaf(v1, v1, v2 * v2));
#pragma unroll
    for (int o = 16; o; o >>= 1) {
        sum += __shfl_xor_sync(0xffffffffu, sum, o);
        sq  += __shfl_xor_sync(0xffffffffu, sq,  o);
    }
    __shared__ float s1[8], s2[8];
    if ((tid & 31) == 0) { s1[tid >> 5] = sum; s2[tid >> 5] = sq; }
    __syncthreads();
    float tsum = 0.f, tsq = 0.f;
#pragma unroll
    for (int i = 0; i < 8; i++) { tsum += s1[i]; tsq += s2[i]; }
    float m = tsum * (1.f / DMODEL);
    float var = tsq * (1.f / DMODEL) - m * m;
    float r = rsqrtf(var + 1e-5f);
    yr[tid]       = (v0 - m) * r * s[tid]       + b[tid];
    yr[tid + 256] = (v1 - m) * r * s[tid + 256] + b[tid + 256];
    yr[tid + 512] = (v2 - m) * r * s[tid + 512] + b[tid + 512];
}

// ---------------- embed assemble ----------------
__global__ __launch_bounds__(256) void assemble_k(
    const float* __restrict__ pos_emb, const float* __restrict__ strain_emb,
    const float* __restrict__ cls_token)
{
    int idx = blockIdx.x * 256 + threadIdx.x;     // 16*513*768 total
    int bt = idx / DMODEL;
    int d = idx - bt * DMODEL;
    int b = bt / SEQL;
    int t = bt - b * SEQL;
    float v = pos_emb[(size_t)t * DMODEL + d];
    // strain branch: concat([strain_emb(385), proj(input2)(128)])
    if (t < STLEN) v += strain_emb[(size_t)t * DMODEL + d];
    else           v += g_ff[((size_t)(8192 + b * NPATCH2 + (t - STLEN))) * DMODEL + d];
    // cls branch: concat([cls(1), proj(input1)(512)])
    if (t == 0)    v += cls_token[d];
    else           v += g_ff[((size_t)(b * NPATCH1 + (t - 1))) * DMODEL + d];
    g_z[idx] = v;
}

// ---------------- qkv de-interleave: col = h*192 + d*3 + {0,1,2} ----------------
__global__ __launch_bounds__(256) void qkv_split_k()
{
    int t = blockIdx.x * 256 + threadIdx.x;       // BATCH*NHEAD*SEQL*DHEAD
    int d = t & (DHEAD - 1);
    int n = (t >> 6) % SEQL;
    int bh = t / (SEQL * DHEAD);
    int h = bh % NHEAD, b = bh / NHEAD;
    size_t src = ((size_t)(b * SEQL + n)) * (3 * DMODEL) + h * (DHEAD * 3) + d * 3;
    g_q[t] = g_qkv[src];
    g_k[t] = g_qkv[src + 1];
    g_v[t] = g_qkv[src + 2];
}

// ---------------- attention scores: S = Q K^T / 8 ----------------
__global__ __launch_bounds__(256) void attn_scores_k()
{
    int bh = blockIdx.y;
    int q0 = blockIdx.x << 6;
    const float* Q = g_q + (size_t)bh * SEQL * DHEAD;
    const float* K = g_k + (size_t)bh * SEQL * DHEAD;
    float* S = g_att + (size_t)bh * SEQL * SEQL;
    __shared__ float Qs[64][68];    // [d][qrow]
    __shared__ float Ks[64][68];    // [d][krow]
    int tid = threadIdx.x;
    int tr = tid >> 4, tc = tid & 15;
#pragma unroll
    for (int i = 0; i < 4; i++) {
        int idx = tid * 4 + i;
        int r = idx >> 4, c4 = (idx & 15) << 2;
        float4 v = make_float4(0.f, 0.f, 0.f, 0.f);
        if (q0 + r < SEQL) v = *(const float4*)(Q + (size_t)(q0 + r) * DHEAD + c4);
        Qs[c4 + 0][r] = v.x; Qs[c4 + 1][r] = v.y; Qs[c4 + 2][r] = v.z; Qs[c4 + 3][r] = v.w;
    }
    for (int k0 = 0; k0 < SEQL; k0 += 64) {
        __syncthreads();
#pragma unroll
        for (int i = 0; i < 4; i++) {
            int idx = tid * 4 + i;
            int r = idx >> 4, c4 = (idx & 15) << 2;
            float4 v = make_float4(0.f, 0.f, 0.f, 0.f);
            if (k0 + r < SEQL) v = *(const float4*)(K + (size_t)(k0 + r) * DHEAD + c4);
            Ks[c4 + 0][r] = v.x; Ks[c4 + 1][r] = v.y; Ks[c4 + 2][r] = v.z; Ks[c4 + 3][r] = v.w;
        }
        __syncthreads();
        float acc[4][4] = {};
#pragma unroll
        for (int d = 0; d < DHEAD; d++) {
            float a4[4], b4[4];
            *(float4*)a4 = *(const float4*)&Qs[d][tr << 2];
            *(float4*)b4 = *(const float4*)&Ks[d][tc << 2];
#pragma unroll
            for (int i = 0; i < 4; i++)
#pragma unroll
                for (int j = 0; j < 4; j++)
                    acc[i][j] = fmaf(a4[i], b4[j], acc[i][j]);
        }
#pragma unroll
        for (int i = 0; i < 4; i++) {
            int qr = q0 + (tr << 2) + i;
            if (qr >= SEQL) continue;
#pragma unroll
            for (int j = 0; j < 4; j++) {
                int kc = k0 + (tc << 2) + j;
                if (kc < SEQL) S[(size_t)qr * SEQL + kc] = acc[i][j] * 0.125f;
            }
        }
    }
}

// ---------------- row softmax over 513 ----------------
__global__ __launch_bounds__(128) void softmax_k()
{
    size_t row = blockIdx.x;
    float* p = g_att + row * SEQL;
    int tid = threadIdx.x;
    float vals[5];
    int cnt = 0;
    float lmax = -3.4e38f;
    for (int i = tid; i < SEQL; i += 128) { float v = p[i]; vals[cnt++] = v; lmax = fmaxf(lmax, v); }
#pragma unroll
    for (int o = 16; o; o >>= 1) lmax = fmaxf(lmax, __shfl_xor_sync(0xffffffffu, lmax, o));
    __shared__ float sm[4], ss[4];
    if ((tid & 31) == 0) sm[tid >> 5] = lmax;
    __syncthreads();
    lmax = fmaxf(fmaxf(sm[0], sm[1]), fmaxf(sm[2], sm[3]));
    float lsum = 0.f;
    for (int j = 0; j < cnt; j++) { vals[j] = expf(vals[j] - lmax); lsum += vals[j]; }
#pragma unroll
    for (int o = 16; o; o >>= 1) lsum += __shfl_xor_sync(0xffffffffu, lsum, o);
    if ((tid & 31) == 0) ss[tid >> 5] = lsum;
    __syncthreads();
    lsum = ss[0] + ss[1] + ss[2] + ss[3];
    float inv = 1.f / lsum;
    cnt = 0;
    for (int i = tid; i < SEQL; i += 128) p[i] = vals[cnt++] * inv;
}

// ---------------- AV: O = softmax(S) @ V, write assembled [b,n,D] ----------------
__global__ __launch_bounds__(256) void attn_av_k()
{
    int bh = blockIdx.y;
    int q0 = blockIdx.x << 6;
    int b = bh / NHEAD, h = bh % NHEAD;
    const float* S = g_att + (size_t)bh * SEQL * SEQL;
    const float* V = g_v + (size_t)bh * SEQL * DHEAD;
    __shared__ float Ss[64][68];    // [k][q]
    __shared__ float Vs[64][68];    // [k][d]
    int tid = threadIdx.x;
    int tr = tid >> 4, tc = tid & 15;
    float acc[4][4] = {};
    for (int k0 = 0; k0 < SEQL; k0 += 64) {
        __syncthreads();
#pragma unroll
        for (int i = 0; i < 4; i++) {
            int idx = tid * 4 + i;
            int r = idx >> 4, c4 = (idx & 15) << 2;
            // S tile (rows 513 floats -> scalar loads, never float4)
            float sv[4] = {0.f, 0.f, 0.f, 0.f};
            if (q0 + r < SEQL) {
                const float* srow = S + (size_t)(q0 + r) * SEQL + k0 + c4;
#pragma unroll
                for (int t = 0; t < 4; t++)
                    if (k0 + c4 + t < SEQL) sv[t] = srow[t];
            }
            Ss[c4 + 0][r] = sv[0]; Ss[c4 + 1][r] = sv[1];
            Ss[c4 + 2][r] = sv[2]; Ss[c4 + 3][r] = sv[3];
            // V tile
            float4 w = make_float4(0.f, 0.f, 0.f, 0.f);
            if (k0 + r < SEQL) w = *(const float4*)(V + (size_t)(k0 + r) * DHEAD + c4);
            *(float4*)&Vs[r][c4] = w;
        }
        __syncthreads();
#pragma unroll
        for (int kk = 0; kk < 64; kk++) {
            float a4[4], b4[4];
            *(float4*)a4 = *(const float4*)&Ss[kk][tr << 2];
            *(float4*)b4 = *(const float4*)&Vs[kk][tc << 2];
#pragma unroll
            for (int i = 0; i < 4; i++)
#pragma unroll
                for (int j = 0; j < 4; j++)
                    acc[i][j] = fmaf(a4[i], b4[j], acc[i][j]);
        }
    }
#pragma unroll
    for (int i = 0; i < 4; i++) {
        int qr = q0 + (tr << 2) + i;
        if (qr >= SEQL) continue;
#pragma unroll
        for (int j = 0; j < 4; j++) {
            int d = (tc << 2) + j;
            g_o[((size_t)(b * SEQL + qr)) * DMODEL + h * DHEAD + d] = acc[i][j];
        }
    }
}

// ---------------- residual add ----------------
__global__ __launch_bounds__(256) void resadd_k()
{
    int idx = blockIdx.x * 256 + threadIdx.x;
    g_z[idx] += g_o[idx];
}

// ---------------- mean pool over tokens ----------------
__global__ __launch_bounds__(256) void pool_k()
{
    int idx = blockIdx.x * 256 + threadIdx.x;     // BATCH*DMODEL = 12288
    int b = idx / DMODEL, d = idx - b * DMODEL;
    const float* p = g_z + (size_t)b * SEQL * DMODEL + d;
    float s = 0.f;
    for (int n = 0; n < SEQL; n++) s += p[(size_t)n * DMODEL];
    g_pool[idx] = s * (1.f / SEQL);
}

// ---------------- tiny head GEMM: one thread per output col ----------------
__global__ void small_gemm_k(const float* __restrict__ A, const float* __restrict__ W,
                             const float* __restrict__ bias, float* __restrict__ C,
                             int N, int K)
{
    int m = blockIdx.x, n = threadIdx.x;
    if (n >= N) return;
    float s = bias[n];
    const float* a = A + (size_t)m * K;
    for (int k = 0; k < K; k++) s = fmaf(a[k], W[(size_t)k * N + n], s);
    C[(size_t)m * N + n] = s;
}

// ---------------- launch ----------------
extern "C" void kernel_launch(void* const* d_in, const int* in_sizes, int n_in,
                              void* d_out, int out_size)
{
    const float* input1     = (const float*)d_in[0];
    const float* input2     = (const float*)d_in[1];
    const float* proj_w     = (const float*)d_in[2];
    const float* proj_b     = (const float*)d_in[3];
    const float* cls_token  = (const float*)d_in[4];
    const float* pos_emb    = (const float*)d_in[5];
    const float* strain_emb = (const float*)d_in[6];
    const float* ln1_s      = (const float*)d_in[7];
    const float* ln1_b      = (const float*)d_in[8];
    const float* wqkv       = (const float*)d_in[9];
    const float* ln2_s      = (const float*)d_in[10];
    const float* ln2_b      = (const float*)d_in[11];
    const float* fc1_w      = (const float*)d_in[12];
    const float* fc1_b      = (const float*)d_in[13];
    const float* fc2_w      = (const float*)d_in[14];
    const float* fc2_b      = (const float*)d_in[15];
    const float* hn_s       = (const float*)d_in[16];
    const float* hn_b       = (const float*)d_in[17];
    const float* h1_w       = (const float*)d_in[18];
    const float* h1_b       = (const float*)d_in[19];
    const float* h2_w       = (const float*)d_in[20];
    const float* h2_b       = (const float*)d_in[21];
    const float* h3_w       = (const float*)d_in[22];
    const float* h3_b       = (const float*)d_in[23];

    float *z, *ln, *qkv, *ff, *pool, *hln, *h1, *h2;
    cudaGetSymbolAddress((void**)&z,    g_z);
    cudaGetSymbolAddress((void**)&ln,   g_ln);
    cudaGetSymbolAddress((void**)&qkv,  g_qkv);
    cudaGetSymbolAddress((void**)&ff,   g_ff);
    cudaGetSymbolAddress((void**)&pool, g_pool);
    cudaGetSymbolAddress((void**)&hln,  g_hln);
    cudaGetSymbolAddress((void**)&h1,   g_h1);
    cudaGetSymbolAddress((void**)&h2,   g_h2);

    const int TOK = BATCH * SEQL;                 // 8208
    const int ELEM_BLKS = (BATCH * SEQL * DMODEL) / 256;  // 24624

    // ---- patch embedding ----
    sgemm128<<<dim3(DMODEL / 128, (BATCH * NPATCH1) / 128), 256>>>(
        input1, proj_w, ff, proj_b, nullptr, BATCH * NPATCH1, DMODEL, PATCHE, 0);
    sgemm128<<<dim3(DMODEL / 128, (BATCH * NPATCH2) / 128), 256>>>(
        input2, proj_w, ff + (size_t)BATCH * NPATCH1 * DMODEL, proj_b, nullptr,
        BATCH * NPATCH2, DMODEL, PATCHE, 0);
    assemble_k<<<ELEM_BLKS, 256>>>(pos_emb, strain_emb, cls_token);

    // ---- transformer layers ----
    for (int l = 0; l < NLAYER; l++) {
        layernorm_k<<<TOK, 256>>>(z, ln, ln1_s + l * DMODEL, ln1_b + l * DMODEL);
        sgemm128<<<dim3((3 * DMODEL) / 128, (TOK + 127) / 128), 256>>>(
            ln, wqkv + (size_t)l * DMODEL * 3 * DMODEL, qkv, nullptr, nullptr,
            TOK, 3 * DMODEL, DMODEL, 0);
        qkv_split_k<<<(BATCH * NHEAD * SEQL * DHEAD) / 256, 256>>>();
        attn_scores_k<<<dim3((SEQL + 63) / 64, BATCH * NHEAD), 256>>>();
        softmax_k<<<BATCH * NHEAD * SEQL, 128>>>();
        attn_av_k<<<dim3((SEQL + 63) / 64, BATCH * NHEAD), 256>>>();
        resadd_k<<<ELEM_BLKS, 256>>>();
        layernorm_k<<<TOK, 256>>>(z, ln, ln2_s + l * DMODEL, ln2_b + l * DMODEL);
        sgemm128<<<dim3(FFDIM / 128, (TOK + 127) / 128), 256>>>(
            ln, fc1_w + (size_t)l * DMODEL * FFDIM, ff, fc1_b + l * FFDIM, nullptr,
            TOK, FFDIM, DMODEL, 1 /*gelu*/);
        sgemm128<<<dim3(DMODEL / 128, (TOK + 127) / 128), 256>>>(
            ff, fc2_w + (size_t)l * FFDIM * DMODEL, z, fc2_b + l * DMODEL, z,
            TOK, DMODEL, FFDIM, 0);
    }

    // ---- head ----
    pool_k<<<(BATCH * DMODEL) / 256, 256>>>();
    layernorm_k<<<BATCH, 256>>>(pool, hln, hn_s, hn_b);
    small_gemm_k<<<BATCH, 256>>>(hln, h1_w, h1_b, h1, 256, DMODEL);
    small_gemm_k<<<BATCH, 64>>>(h1, h2_w, h2_b, h2, 64, 256);
    small_gemm_k<<<BATCH, 32>>>(h2, h3_w, h3_b, (float*)d_out, 1, 64);
}

// round 2
// speedup vs baseline: 1.0639x; 1.0639x over previous
#include <cuda_runtime.h>
#include <math.h>

// ---------------- problem constants ----------------
#define BATCH 16
#define SEQL  513
#define DMODEL 768
#define NHEAD 12
#define DHEAD 64
#define FFDIM 3072
#define NLAYER 12
#define NPATCH1 512
#define NPATCH2 128
#define PATCHE 256      // 16*16
#define STLEN 385       // NPATCH - NSP + 1

// ---------------- packed fp32x2 helpers (Blackwell FFMA2 pipe) ----------------
__device__ __forceinline__ unsigned long long dup2(float x) {
    unsigned long long r; unsigned u = __float_as_uint(x);
    asm("mov.b64 %0, {%1, %1};" : "=l"(r) : "r"(u));
    return r;
}
__device__ __forceinline__ unsigned long long ffma2(
    unsigned long long a, unsigned long long b, unsigned long long c) {
    unsigned long long d;
    asm("fma.rn.f32x2 %0, %1, %2, %3;" : "=l"(d) : "l"(a), "l"(b), "l"(c));
    return d;
}
__device__ __forceinline__ float2 unp2(unsigned long long v) {
    unsigned lo, hi;
    asm("mov.b64 {%0, %1}, %2;" : "=r"(lo), "=r"(hi) : "l"(v));
    return make_float2(__uint_as_float(lo), __uint_as_float(hi));
}

// ---------------- scratch (device globals; no runtime alloc) ----------------
__device__ float g_z  [BATCH*SEQL*DMODEL];          // residual stream
__device__ float g_ln [BATCH*SEQL*DMODEL];          // layernorm output
__device__ float g_qkv[BATCH*SEQL*3*DMODEL];        // qkv projection
__device__ float g_q  [BATCH*NHEAD*SEQL*DHEAD];
__device__ float g_k  [BATCH*NHEAD*SEQL*DHEAD];
__device__ float g_v  [BATCH*NHEAD*SEQL*DHEAD];
__device__ float g_att[(size_t)BATCH*NHEAD*SEQL*SEQL];  // attention scores/probs
__device__ float g_o  [BATCH*SEQL*DMODEL];          // attention output (assembled)
__device__ float g_ff [BATCH*SEQL*FFDIM];           // FF hidden / embed scratch
__device__ float g_pool[BATCH*DMODEL];
__device__ float g_hln [BATCH*DMODEL];
__device__ float g_h1  [BATCH*256];
__device__ float g_h2  [BATCH*64];

// ---------------- generic fp32 GEMM (FFMA2): C = A@B (+bias)(+gelu)(+res) ----
// Requirements: K % 8 == 0, N % 128 == 0 (true for all call sites). M ragged OK.
__global__ __launch_bounds__(256) void sgemm128(
    const float* __restrict__ A, const float* __restrict__ B,
    float* __restrict__ C, const float* __restrict__ bias,
    const float* __restrict__ res, int M, int N, int K, int act)
{
    __shared__ float As[8][128];
    __shared__ float Bs[8][128];
    const int tid = threadIdx.x;
    const int row0 = blockIdx.y * 128;
    const int col0 = blockIdx.x * 128;
    const int tr = tid >> 4;        // 0..15
    const int tc = tid & 15;        // 0..15

    unsigned long long acc2[8][4];
#pragma unroll
    for (int i = 0; i < 8; i++)
#pragma unroll
        for (int j = 0; j < 4; j++) acc2[i][j] = 0ull;

    const int arow = tid >> 1;            // 0..127
    const int acol = (tid & 1) << 2;      // 0 or 4
    const int brow = tid >> 5;            // 0..7
    const int bcol = (tid & 31) << 2;     // 0..124

    const bool avalid = (row0 + arow) < M;
    const float* Aptr = A + (size_t)(row0 + arow) * K + acol;
    const float* Bptr = B + (size_t)brow * N + col0 + bcol;

    for (int k0 = 0; k0 < K; k0 += 8) {
        float4 av = make_float4(0.f, 0.f, 0.f, 0.f);
        if (avalid) av = *(const float4*)(Aptr + k0);
        float4 bv = *(const float4*)(Bptr + (size_t)k0 * N);
        __syncthreads();
        As[acol + 0][arow] = av.x;
        As[acol + 1][arow] = av.y;
        As[acol + 2][arow] = av.z;
        As[acol + 3][arow] = av.w;
        *(float4*)&Bs[brow][bcol] = bv;
        __syncthreads();
#pragma unroll
        for (int kk = 0; kk < 8; kk++) {
            float a[8];
            *(float4*)(a)     = *(const float4*)&As[kk][tr * 8];
            *(float4*)(a + 4) = *(const float4*)&As[kk][tr * 8 + 4];
            ulonglong2 b01 = *(const ulonglong2*)&Bs[kk][tc * 8];
            ulonglong2 b23 = *(const ulonglong2*)&Bs[kk][tc * 8 + 4];
            unsigned long long bp0 = b01.x, bp1 = b01.y, bp2 = b23.x, bp3 = b23.y;
#pragma unroll
            for (int i = 0; i < 8; i++) {
                unsigned long long ai = dup2(a[i]);
                acc2[i][0] = ffma2(ai, bp0, acc2[i][0]);
                acc2[i][1] = ffma2(ai, bp1, acc2[i][1]);
                acc2[i][2] = ffma2(ai, bp2, acc2[i][2]);
                acc2[i][3] = ffma2(ai, bp3, acc2[i][3]);
            }
        }
    }

#pragma unroll
    for (int i = 0; i < 8; i++) {
        int r = row0 + tr * 8 + i;
        if (r >= M) continue;
#pragma unroll
        for (int j2 = 0; j2 < 4; j2++) {
            float2 v2 = unp2(acc2[i][j2]);
            int c0 = col0 + tc * 8 + 2 * j2;
            float v[2] = {v2.x, v2.y};
#pragma unroll
            for (int t = 0; t < 2; t++) {
                int c = c0 + t;
                float vv = v[t];
                if (bias) vv += bias[c];
                if (act)  vv = vv * normcdff(vv);   // exact GELU: x * Phi(x)
                if (res)  vv += res[(size_t)r * N + c];
                C[(size_t)r * N + c] = vv;
            }
        }
    }
}

// ---------------- layernorm: one block per row of 768 ----------------
__global__ __launch_bounds__(256) void layernorm_k(
    const float* __restrict__ x, float* __restrict__ y,
    const float* __restrict__ s, const float* __restrict__ b)
{
    int row = blockIdx.x;
    const float* xr = x + (size_t)row * DMODEL;
    float* yr = y + (size_t)row * DMODEL;
    int tid = threadIdx.x;
    float v0 = xr[tid], v1 = xr[tid + 256], v2 = xr[tid + 512];
    float sum = v0 + v1 + v2;
    float sq  = fmaf(v0, v0, fmaf(v1, v1, v2 * v2));
#pragma unroll
    for (int o = 16; o; o >>= 1) {
        sum += __shfl_xor_sync(0xffffffffu, sum, o);
        sq  += __shfl_xor_sync(0xffffffffu, sq,  o);
    }
    __shared__ float s1[8], s2[8];
    if ((tid & 31) == 0) { s1[tid >> 5] = sum; s2[tid >> 5] = sq; }
    __syncthreads();
    float tsum = 0.f, tsq = 0.f;
#pragma unroll
    for (int i = 0; i < 8; i++) { tsum += s1[i]; tsq += s2[i]; }
    float m = tsum * (1.f / DMODEL);
    float var = tsq * (1.f / DMODEL) - m * m;
    float r = rsqrtf(var + 1e-5f);
    yr[tid]       = (v0 - m) * r * s[tid]       + b[tid];
    yr[tid + 256] = (v1 - m) * r * s[tid + 256] + b[tid + 256];
    yr[tid + 512] = (v2 - m) * r * s[tid + 512] + b[tid + 512];
}

// ---------------- embed assemble ----------------
__global__ __launch_bounds__(256) void assemble_k(
    const float* __restrict__ pos_emb, const float* __restrict__ strain_emb,
    const float* __restrict__ cls_token)
{
    int idx = blockIdx.x * 256 + threadIdx.x;     // 16*513*768 total
    int bt = idx / DMODEL;
    int d = idx - bt * DMODEL;
    int b = bt / SEQL;
    int t = bt - b * SEQL;
    float v = pos_emb[(size_t)t * DMODEL + d];
    // strain branch: concat([strain_emb(385), proj(input2)(128)])
    if (t < STLEN) v += strain_emb[(size_t)t * DMODEL + d];
    else           v += g_ff[((size_t)(8192 + b * NPATCH2 + (t - STLEN))) * DMODEL + d];
    // cls branch: concat([cls(1), proj(input1)(512)])
    if (t == 0)    v += cls_token[d];
    else           v += g_ff[((size_t)(b * NPATCH1 + (t - 1))) * DMODEL + d];
    g_z[idx] = v;
}

// ---------------- qkv de-interleave: col = h*192 + d*3 + {0,1,2} ----------------
__global__ __launch_bounds__(256) void qkv_split_k()
{
    int t = blockIdx.x * 256 + threadIdx.x;       // BATCH*NHEAD*SEQL*DHEAD
    int d = t & (DHEAD - 1);
    int n = (t >> 6) % SEQL;
    int bh = t / (SEQL * DHEAD);
    int h = bh % NHEAD, b = bh / NHEAD;
    size_t src = ((size_t)(b * SEQL + n)) * (3 * DMODEL) + h * (DHEAD * 3) + d * 3;
    g_q[t] = g_qkv[src];
    g_k[t] = g_qkv[src + 1];
    g_v[t] = g_qkv[src + 2];
}

// ---------------- attention scores: S = Q K^T / 8 ----------------
__global__ __launch_bounds__(256) void attn_scores_k()
{
    int bh = blockIdx.y;
    int q0 = blockIdx.x << 6;
    const float* Q = g_q + (size_t)bh * SEQL * DHEAD;
    const float* K = g_k + (size_t)bh * SEQL * DHEAD;
    float* S = g_att + (size_t)bh * SEQL * SEQL;
    __shared__ float Qs[64][68];    // [d][qrow]
    __shared__ float Ks[64][68];    // [d][krow]
    int tid = threadIdx.x;
    int tr = tid >> 4, tc = tid & 15;
#pragma unroll
    for (int i = 0; i < 4; i++) {
        int idx = tid * 4 + i;
        int r = idx >> 4, c4 = (idx & 15) << 2;
        float4 v = make_float4(0.f, 0.f, 0.f, 0.f);
        if (q0 + r < SEQL) v = *(const float4*)(Q + (size_t)(q0 + r) * DHEAD + c4);
        Qs[c4 + 0][r] = v.x; Qs[c4 + 1][r] = v.y; Qs[c4 + 2][r] = v.z; Qs[c4 + 3][r] = v.w;
    }
    for (int k0 = 0; k0 < SEQL; k0 += 64) {
        __syncthreads();
#pragma unroll
        for (int i = 0; i < 4; i++) {
            int idx = tid * 4 + i;
            int r = idx >> 4, c4 = (idx & 15) << 2;
            float4 v = make_float4(0.f, 0.f, 0.f, 0.f);
            if (k0 + r < SEQL) v = *(const float4*)(K + (size_t)(k0 + r) * DHEAD + c4);
            Ks[c4 + 0][r] = v.x; Ks[c4 + 1][r] = v.y; Ks[c4 + 2][r] = v.z; Ks[c4 + 3][r] = v.w;
        }
        __syncthreads();
        unsigned long long acc2[4][2];
#pragma unroll
        for (int i = 0; i < 4; i++) { acc2[i][0] = 0ull; acc2[i][1] = 0ull; }
#pragma unroll
        for (int d = 0; d < DHEAD; d++) {
            float a4[4];
            *(float4*)a4 = *(const float4*)&Qs[d][tr << 2];
            ulonglong2 bb = *(const ulonglong2*)&Ks[d][tc << 2];
#pragma unroll
            for (int i = 0; i < 4; i++) {
                unsigned long long ai = dup2(a4[i]);
                acc2[i][0] = ffma2(ai, bb.x, acc2[i][0]);
                acc2[i][1] = ffma2(ai, bb.y, acc2[i][1]);
            }
        }
#pragma unroll
        for (int i = 0; i < 4; i++) {
            int qr = q0 + (tr << 2) + i;
            if (qr >= SEQL) continue;
#pragma unroll
            for (int j2 = 0; j2 < 2; j2++) {
                float2 v2 = unp2(acc2[i][j2]);
                int kc = k0 + (tc << 2) + 2 * j2;
                if (kc < SEQL)     S[(size_t)qr * SEQL + kc]     = v2.x * 0.125f;
                if (kc + 1 < SEQL) S[(size_t)qr * SEQL + kc + 1] = v2.y * 0.125f;
            }
        }
    }
}

// ---------------- row softmax over 513 ----------------
__global__ __launch_bounds__(128) void softmax_k()
{
    size_t row = blockIdx.x;
    float* p = g_att + row * SEQL;
    int tid = threadIdx.x;
    float vals[5];
    int cnt = 0;
    float lmax = -3.4e38f;
    for (int i = tid; i < SEQL; i += 128) { float v = p[i]; vals[cnt++] = v; lmax = fmaxf(lmax, v); }
#pragma unroll
    for (int o = 16; o; o >>= 1) lmax = fmaxf(lmax, __shfl_xor_sync(0xffffffffu, lmax, o));
    __shared__ float sm[4], ss[4];
    if ((tid & 31) == 0) sm[tid >> 5] = lmax;
    __syncthreads();
    lmax = fmaxf(fmaxf(sm[0], sm[1]), fmaxf(sm[2], sm[3]));
    float lsum = 0.f;
    for (int j = 0; j < cnt; j++) { vals[j] = expf(vals[j] - lmax); lsum += vals[j]; }
#pragma unroll
    for (int o = 16; o; o >>= 1) lsum += __shfl_xor_sync(0xffffffffu, lsum, o);
    if ((tid & 31) == 0) ss[tid >> 5] = lsum;
    __syncthreads();
    lsum = ss[0] + ss[1] + ss[2] + ss[3];
    float inv = 1.f / lsum;
    cnt = 0;
    for (int i = tid; i < SEQL; i += 128) p[i] = vals[cnt++] * inv;
}

// ---------------- AV: O = softmax(S) @ V, write assembled [b,n,D] ----------------
__global__ __launch_bounds__(256) void attn_av_k()
{
    int bh = blockIdx.y;
    int q0 = blockIdx.x << 6;
    int b = bh / NHEAD, h = bh % NHEAD;
    const float* S = g_att + (size_t)bh * SEQL * SEQL;
    const float* V = g_v + (size_t)bh * SEQL * DHEAD;
    __shared__ float Ss[64][68];    // [k][q]
    __shared__ float Vs[64][68];    // [k][d]
    int tid = threadIdx.x;
    int tr = tid >> 4, tc = tid & 15;
    unsigned long long acc2[4][2];
#pragma unroll
    for (int i = 0; i < 4; i++) { acc2[i][0] = 0ull; acc2[i][1] = 0ull; }
    for (int k0 = 0; k0 < SEQL; k0 += 64) {
        __syncthreads();
#pragma unroll
        for (int i = 0; i < 4; i++) {
            int idx = tid * 4 + i;
            int r = idx >> 4, c4 = (idx & 15) << 2;
            // S tile (rows 513 floats -> scalar loads, never float4)
            float sv[4] = {0.f, 0.f, 0.f, 0.f};
            if (q0 + r < SEQL) {
                const float* srow = S + (size_t)(q0 + r) * SEQL + k0 + c4;
#pragma unroll
                for (int t = 0; t < 4; t++)
                    if (k0 + c4 + t < SEQL) sv[t] = srow[t];
            }
            Ss[c4 + 0][r] = sv[0]; Ss[c4 + 1][r] = sv[1];
            Ss[c4 + 2][r] = sv[2]; Ss[c4 + 3][r] = sv[3];
            // V tile
            float4 w = make_float4(0.f, 0.f, 0.f, 0.f);
            if (k0 + r < SEQL) w = *(const float4*)(V + (size_t)(k0 + r) * DHEAD + c4);
            *(float4*)&Vs[r][c4] = w;
        }
        __syncthreads();
#pragma unroll
        for (int kk = 0; kk < 64; kk++) {
            float a4[4];
            *(float4*)a4 = *(const float4*)&Ss[kk][tr << 2];
            ulonglong2 bb = *(const ulonglong2*)&Vs[kk][tc << 2];
#pragma unroll
            for (int i = 0; i < 4; i++) {
                unsigned long long ai = dup2(a4[i]);
                acc2[i][0] = ffma2(ai, bb.x, acc2[i][0]);
                acc2[i][1] = ffma2(ai, bb.y, acc2[i][1]);
            }
        }
    }
#pragma unroll
    for (int i = 0; i < 4; i++) {
        int qr = q0 + (tr << 2) + i;
        if (qr >= SEQL) continue;
#pragma unroll
        for (int j2 = 0; j2 < 2; j2++) {
            float2 v2 = unp2(acc2[i][j2]);
            int d = (tc << 2) + 2 * j2;
            size_t base = ((size_t)(b * SEQL + qr)) * DMODEL + h * DHEAD + d;
            g_o[base]     = v2.x;
            g_o[base + 1] = v2.y;
        }
    }
}

// ---------------- residual add ----------------
__global__ __launch_bounds__(256) void resadd_k()
{
    int idx = blockIdx.x * 256 + threadIdx.x;
    g_z[idx] += g_o[idx];
}

// ---------------- mean pool over tokens ----------------
__global__ __launch_bounds__(256) void pool_k()
{
    int idx = blockIdx.x * 256 + threadIdx.x;     // BATCH*DMODEL = 12288
    int b = idx / DMODEL, d = idx - b * DMODEL;
    const float* p = g_z + (size_t)b * SEQL * DMODEL + d;
    float s = 0.f;
    for (int n = 0; n < SEQL; n++) s += p[(size_t)n * DMODEL];
    g_pool[idx] = s * (1.f / SEQL);
}

// ---------------- tiny head GEMM: one thread per output col ----------------
__global__ void small_gemm_k(const float* __restrict__ A, const float* __restrict__ W,
                             const float* __restrict__ bias, float* __restrict__ C,
                             int N, int K)
{
    int m = blockIdx.x, n = threadIdx.x;
    if (n >= N) return;
    float s = bias[n];
    const float* a = A + (size_t)m * K;
    for (int k = 0; k < K; k++) s = fmaf(a[k], W[(size_t)k * N + n], s);
    C[(size_t)m * N + n] = s;
}

// ---------------- launch ----------------
extern "C" void kernel_launch(void* const* d_in, const int* in_sizes, int n_in,
                              void* d_out, int out_size)
{
    const float* input1     = (const float*)d_in[0];
    const float* input2     = (const float*)d_in[1];
    const float* proj_w     = (const float*)d_in[2];
    const float* proj_b     = (const float*)d_in[3];
    const float* cls_token  = (const float*)d_in[4];
    const float* pos_emb    = (const float*)d_in[5];
    const float* strain_emb = (const float*)d_in[6];
    const float* ln1_s      = (const float*)d_in[7];
    const float* ln1_b      = (const float*)d_in[8];
    const float* wqkv       = (const float*)d_in[9];
    const float* ln2_s      = (const float*)d_in[10];
    const float* ln2_b      = (const float*)d_in[11];
    const float* fc1_w      = (const float*)d_in[12];
    const float* fc1_b      = (const float*)d_in[13];
    const float* fc2_w      = (const float*)d_in[14];
    const float* fc2_b      = (const float*)d_in[15];
    const float* hn_s       = (const float*)d_in[16];
    const float* hn_b       = (const float*)d_in[17];
    const float* h1_w       = (const float*)d_in[18];
    const float* h1_b       = (const float*)d_in[19];
    const float* h2_w       = (const float*)d_in[20];
    const float* h2_b       = (const float*)d_in[21];
    const float* h3_w       = (const float*)d_in[22];
    const float* h3_b       = (const float*)d_in[23];

    float *z, *ln, *qkv, *ff, *pool, *hln, *h1, *h2;
    cudaGetSymbolAddress((void**)&z,    g_z);
    cudaGetSymbolAddress((void**)&ln,   g_ln);
    cudaGetSymbolAddress((void**)&qkv,  g_qkv);
    cudaGetSymbolAddress((void**)&ff,   g_ff);
    cudaGetSymbolAddress((void**)&pool, g_pool);
    cudaGetSymbolAddress((void**)&hln,  g_hln);
    cudaGetSymbolAddress((void**)&h1,   g_h1);
    cudaGetSymbolAddress((void**)&h2,   g_h2);

    const int TOK = BATCH * SEQL;                 // 8208
    const int ELEM_BLKS = (BATCH * SEQL * DMODEL) / 256;  // 24624

    // ---- patch embedding ----
    sgemm128<<<dim3(DMODEL / 128, (BATCH * NPATCH1) / 128), 256>>>(
        input1, proj_w, ff, proj_b, nullptr, BATCH * NPATCH1, DMODEL, PATCHE, 0);
    sgemm128<<<dim3(DMODEL / 128, (BATCH * NPATCH2) / 128), 256>>>(
        input2, proj_w, ff + (size_t)BATCH * NPATCH1 * DMODEL, proj_b, nullptr,
        BATCH * NPATCH2, DMODEL, PATCHE, 0);
    assemble_k<<<ELEM_BLKS, 256>>>(pos_emb, strain_emb, cls_token);

    // ---- transformer layers ----
    for (int l = 0; l < NLAYER; l++) {
        layernorm_k<<<TOK, 256>>>(z, ln, ln1_s + l * DMODEL, ln1_b + l * DMODEL);
        sgemm128<<<dim3((3 * DMODEL) / 128, (TOK + 127) / 128), 256>>>(
            ln, wqkv + (size_t)l * DMODEL * 3 * DMODEL, qkv, nullptr, nullptr,
            TOK, 3 * DMODEL, DMODEL, 0);
        qkv_split_k<<<(BATCH * NHEAD * SEQL * DHEAD) / 256, 256>>>();
        attn_scores_k<<<dim3((SEQL + 63) / 64, BATCH * NHEAD), 256>>>();
        softmax_k<<<BATCH * NHEAD * SEQL, 128>>>();
        attn_av_k<<<dim3((SEQL + 63) / 64, BATCH * NHEAD), 256>>>();
        resadd_k<<<ELEM_BLKS, 256>>>();
        layernorm_k<<<TOK, 256>>>(z, ln, ln2_s + l * DMODEL, ln2_b + l * DMODEL);
        sgemm128<<<dim3(FFDIM / 128, (TOK + 127) / 128), 256>>>(
            ln, fc1_w + (size_t)l * DMODEL * FFDIM, ff, fc1_b + l * FFDIM, nullptr,
            TOK, FFDIM, DMODEL, 1 /*gelu*/);
        sgemm128<<<dim3(DMODEL / 128, (TOK + 127) / 128), 256>>>(
            ff, fc2_w + (size_t)l * FFDIM * DMODEL, z, fc2_b + l * DMODEL, z,
            TOK, DMODEL, FFDIM, 0);
    }

    // ---- head ----
    pool_k<<<(BATCH * DMODEL) / 256, 256>>>();
    layernorm_k<<<BATCH, 256>>>(pool, hln, hn_s, hn_b);
    small_gemm_k<<<BATCH, 256>>>(hln, h1_w, h1_b, h1, 256, DMODEL);
    small_gemm_k<<<BATCH, 64>>>(h1, h2_w, h2_b, h2, 64, 256);
    small_gemm_k<<<BATCH, 32>>>(h2, h3_w, h3_b, (float*)d_out, 1, 64);
}